// round 1
// baseline (speedup 1.0000x reference)
#include <cuda_runtime.h>
#include <math.h>

#define BB 8
#define TT 2048
#define CC 512
#define UU 256
#define BT (BB*TT)

// Scratch (allocation-free rule: device globals)
__device__ float g_Q[BT*UU];
__device__ float g_K[BT*UU];
__device__ float g_V[BT*UU];
__device__ float g_A[BT*UU];

// ---------------------------------------------------------------------------
// Kernel 1: fused QKV projection.  [BT, C] @ [C, U] x3, shared x tile.
// Tiles: M=64 (rows of BT), N=64 (cols of U), K-chunk=16. 256 threads, 4x4 micro.
// ---------------------------------------------------------------------------
__global__ __launch_bounds__(256) void qkv_kernel(
    const float* __restrict__ x,
    const float* __restrict__ Wq, const float* __restrict__ bq,
    const float* __restrict__ Wk, const float* __restrict__ bk,
    const float* __restrict__ Wv, const float* __restrict__ bv)
{
    __shared__ float Xs[16][68];      // [k][m], padded
    __shared__ float Wqs[16][68];     // [k][n]
    __shared__ float Wks[16][68];
    __shared__ float Wvs[16][68];

    const int m0 = blockIdx.x * 64;
    const int n0 = blockIdx.y * 64;
    const int tid = threadIdx.x;
    const int tm = tid >> 4;          // 0..15
    const int tn = tid & 15;          // 0..15

    // loader indices
    const int lr  = tid >> 2;         // 0..63 (x row within tile)
    const int lc4 = (tid & 3) * 4;    // 0,4,8,12 (k offset)
    const int wk  = tid >> 4;         // 0..15 (W row within k-chunk)
    const int wn4 = (tid & 15) * 4;   // 0..60 (n offset)

    float aq[4][4] = {}, ak[4][4] = {}, av[4][4] = {};

    for (int k0 = 0; k0 < CC; k0 += 16) {
        __syncthreads();
        // x tile: 64 rows x 16 k
        float4 xv = *reinterpret_cast<const float4*>(&x[(size_t)(m0 + lr) * CC + k0 + lc4]);
        Xs[lc4 + 0][lr] = xv.x;
        Xs[lc4 + 1][lr] = xv.y;
        Xs[lc4 + 2][lr] = xv.z;
        Xs[lc4 + 3][lr] = xv.w;
        // weight tiles: 16 k x 64 n
        float4 wq4 = *reinterpret_cast<const float4*>(&Wq[(size_t)(k0 + wk) * UU + n0 + wn4]);
        float4 wk4 = *reinterpret_cast<const float4*>(&Wk[(size_t)(k0 + wk) * UU + n0 + wn4]);
        float4 wv4 = *reinterpret_cast<const float4*>(&Wv[(size_t)(k0 + wk) * UU + n0 + wn4]);
        Wqs[wk][wn4 + 0] = wq4.x; Wqs[wk][wn4 + 1] = wq4.y; Wqs[wk][wn4 + 2] = wq4.z; Wqs[wk][wn4 + 3] = wq4.w;
        Wks[wk][wn4 + 0] = wk4.x; Wks[wk][wn4 + 1] = wk4.y; Wks[wk][wn4 + 2] = wk4.z; Wks[wk][wn4 + 3] = wk4.w;
        Wvs[wk][wn4 + 0] = wv4.x; Wvs[wk][wn4 + 1] = wv4.y; Wvs[wk][wn4 + 2] = wv4.z; Wvs[wk][wn4 + 3] = wv4.w;
        __syncthreads();

        #pragma unroll
        for (int k = 0; k < 16; k++) {
            float a[4];
            #pragma unroll
            for (int i = 0; i < 4; i++) a[i] = Xs[k][tm * 4 + i];
            float q4[4], k4[4], v4[4];
            #pragma unroll
            for (int j = 0; j < 4; j++) {
                q4[j] = Wqs[k][tn * 4 + j];
                k4[j] = Wks[k][tn * 4 + j];
                v4[j] = Wvs[k][tn * 4 + j];
            }
            #pragma unroll
            for (int i = 0; i < 4; i++)
                #pragma unroll
                for (int j = 0; j < 4; j++) {
                    aq[i][j] = fmaf(a[i], q4[j], aq[i][j]);
                    ak[i][j] = fmaf(a[i], k4[j], ak[i][j]);
                    av[i][j] = fmaf(a[i], v4[j], av[i][j]);
                }
        }
    }

    #pragma unroll
    for (int i = 0; i < 4; i++) {
        const int m = m0 + tm * 4 + i;
        #pragma unroll
        for (int j = 0; j < 4; j++) {
            const int n = n0 + tn * 4 + j;
            g_Q[(size_t)m * UU + n] = aq[i][j] + bq[n];
            g_K[(size_t)m * UU + n] = ak[i][j] + bk[n];
            g_V[(size_t)m * UU + n] = av[i][j] + bv[n];
        }
    }
}

// ---------------------------------------------------------------------------
// Kernel 2: flash attention.  Per block: 32 queries of one batch, full U=256.
// Key tiles of 64, online softmax, PV accumulated in registers.
// ---------------------------------------------------------------------------
#define TQ 32
#define TK 64
#define KV_STRIDE 257
#define ATTN_SMEM_FLOATS (TQ*UU + TK*KV_STRIDE + TQ*65 + 3*TQ)
#define ATTN_SMEM_BYTES  (ATTN_SMEM_FLOATS * 4)

__global__ __launch_bounds__(256) void attn_kernel()
{
    extern __shared__ float sm[];
    float* Qs   = sm;                       // TQ * UU  (scaled q)
    float* KVs  = Qs + TQ * UU;             // TK * KV_STRIDE (K chunk / V tile)
    float* Ps   = KVs + TK * KV_STRIDE;     // TQ * 65  (scores -> probs)
    float* mrow = Ps + TQ * 65;             // TQ running max
    float* lrow = mrow + TQ;                // TQ running denom
    float* crow = lrow + TQ;                // TQ correction

    const int b   = blockIdx.y;
    const int q0  = blockIdx.x * TQ;
    const int tid = threadIdx.x;

    const float scale = 0.0625f;            // 1/sqrt(256)

    // load Q tile (scaled)
    for (int i = tid; i < TQ * UU; i += 256) {
        const int q = i >> 8;               // /UU
        const int u = i & (UU - 1);
        Qs[i] = g_Q[(size_t)(b * TT + q0 + q) * UU + u] * scale;
    }
    if (tid < TQ) { mrow[tid] = -1e30f; lrow[tid] = 0.0f; }

    // O accumulator: thread owns query oq, dims dg + 8*i
    const int oq = tid >> 3;                // 0..31
    const int dg = tid & 7;                 // 0..7
    float O[32];
    #pragma unroll
    for (int i = 0; i < 32; i++) O[i] = 0.0f;

    // S micro-tile ownership: 2 q-rows x 4 k-cols
    const int tq2 = (tid >> 4) * 2;         // 0,2,...,30
    const int tk4 = (tid & 15) * 4;         // 0,4,...,60

    __syncthreads();

    for (int s0 = 0; s0 < TT; s0 += TK) {
        float Sacc[2][4] = {};

        // --- S = Qs @ K^T over 4 u-chunks of 64 ---
        for (int uc = 0; uc < UU; uc += 64) {
            __syncthreads();                // KVs free (prev users done)
            for (int i = tid; i < TK * 64; i += 256) {
                const int key = i >> 6;
                const int u   = i & 63;
                KVs[key * KV_STRIDE + u] = g_K[(size_t)(b * TT + s0 + key) * UU + uc + u];
            }
            __syncthreads();
            #pragma unroll 4
            for (int u = 0; u < 64; u++) {
                const float a0 = Qs[tq2 * UU + uc + u];
                const float a1 = Qs[(tq2 + 1) * UU + uc + u];
                #pragma unroll
                for (int j = 0; j < 4; j++) {
                    const float bv_ = KVs[(tk4 + j) * KV_STRIDE + u];
                    Sacc[0][j] = fmaf(a0, bv_, Sacc[0][j]);
                    Sacc[1][j] = fmaf(a1, bv_, Sacc[1][j]);
                }
            }
        }

        // stage S into smem
        #pragma unroll
        for (int j = 0; j < 4; j++) {
            Ps[tq2 * 65 + tk4 + j]       = Sacc[0][j];
            Ps[(tq2 + 1) * 65 + tk4 + j] = Sacc[1][j];
        }
        __syncthreads();

        // --- online softmax (one thread per query row) ---
        if (tid < TQ) {
            const float m_old = mrow[tid];
            float rmax = m_old;
            #pragma unroll 8
            for (int k = 0; k < TK; k++) rmax = fmaxf(rmax, Ps[tid * 65 + k]);
            const float cc = __expf(m_old - rmax);
            float sum = 0.0f;
            #pragma unroll 8
            for (int k = 0; k < TK; k++) {
                const float p = __expf(Ps[tid * 65 + k] - rmax);
                Ps[tid * 65 + k] = p;
                sum += p;
            }
            lrow[tid] = lrow[tid] * cc + sum;
            mrow[tid] = rmax;
            crow[tid] = cc;
        }
        __syncthreads();

        // rescale O
        const float cc = crow[oq];
        #pragma unroll
        for (int i = 0; i < 32; i++) O[i] *= cc;

        // load full V tile [64][256]
        for (int i = tid; i < TK * UU; i += 256) {
            const int key = i >> 8;
            const int d   = i & (UU - 1);
            KVs[key * KV_STRIDE + d] = g_V[(size_t)(b * TT + s0 + key) * UU + d];
        }
        __syncthreads();

        // O += P @ V
        #pragma unroll 2
        for (int s = 0; s < TK; s++) {
            const float p = Ps[oq * 65 + s];
            const float* vrow = &KVs[s * KV_STRIDE + dg];
            #pragma unroll
            for (int i = 0; i < 32; i++)
                O[i] = fmaf(p, vrow[i * 8], O[i]);
        }
        // next tile's first __syncthreads protects KVs/Ps reuse
    }

    const float inv = 1.0f / lrow[oq];
    #pragma unroll
    for (int i = 0; i < 32; i++)
        g_A[(size_t)(b * TT + q0 + oq) * UU + dg + i * 8] = O[i] * inv;
}

// ---------------------------------------------------------------------------
// Kernel 3: output projection + residual.  out = x + A @ Wa + ba
// [BT,256] @ [256,512]. Same tiling as kernel 1.
// ---------------------------------------------------------------------------
__global__ __launch_bounds__(256) void proj_kernel(
    const float* __restrict__ x,
    const float* __restrict__ Wa, const float* __restrict__ ba,
    float* __restrict__ out)
{
    __shared__ float As[16][68];
    __shared__ float Ws[16][68];

    const int m0 = blockIdx.x * 64;
    const int n0 = blockIdx.y * 64;
    const int tid = threadIdx.x;
    const int tm = tid >> 4;
    const int tn = tid & 15;

    const int lr  = tid >> 2;
    const int lc4 = (tid & 3) * 4;
    const int wk  = tid >> 4;
    const int wn4 = (tid & 15) * 4;

    float acc[4][4] = {};

    for (int k0 = 0; k0 < UU; k0 += 16) {
        __syncthreads();
        float4 av = *reinterpret_cast<const float4*>(&g_A[(size_t)(m0 + lr) * UU + k0 + lc4]);
        As[lc4 + 0][lr] = av.x;
        As[lc4 + 1][lr] = av.y;
        As[lc4 + 2][lr] = av.z;
        As[lc4 + 3][lr] = av.w;
        float4 wv = *reinterpret_cast<const float4*>(&Wa[(size_t)(k0 + wk) * CC + n0 + wn4]);
        Ws[wk][wn4 + 0] = wv.x; Ws[wk][wn4 + 1] = wv.y; Ws[wk][wn4 + 2] = wv.z; Ws[wk][wn4 + 3] = wv.w;
        __syncthreads();

        #pragma unroll
        for (int k = 0; k < 16; k++) {
            float a[4];
            #pragma unroll
            for (int i = 0; i < 4; i++) a[i] = As[k][tm * 4 + i];
            float w4[4];
            #pragma unroll
            for (int j = 0; j < 4; j++) w4[j] = Ws[k][tn * 4 + j];
            #pragma unroll
            for (int i = 0; i < 4; i++)
                #pragma unroll
                for (int j = 0; j < 4; j++)
                    acc[i][j] = fmaf(a[i], w4[j], acc[i][j]);
        }
    }

    #pragma unroll
    for (int i = 0; i < 4; i++) {
        const int m = m0 + tm * 4 + i;
        #pragma unroll
        for (int j = 0; j < 4; j++) {
            const int n = n0 + tn * 4 + j;
            out[(size_t)m * CC + n] = acc[i][j] + x[(size_t)m * CC + n] + ba[n];
        }
    }
}

// ---------------------------------------------------------------------------
extern "C" void kernel_launch(void* const* d_in, const int* in_sizes, int n_in,
                              void* d_out, int out_size)
{
    const float* x  = (const float*)d_in[0];
    const float* Wq = (const float*)d_in[1];
    const float* bq = (const float*)d_in[2];
    const float* Wk = (const float*)d_in[3];
    const float* bk = (const float*)d_in[4];
    const float* Wv = (const float*)d_in[5];
    const float* bv = (const float*)d_in[6];
    const float* Wa = (const float*)d_in[7];
    const float* ba = (const float*)d_in[8];
    float* out = (float*)d_out;

    qkv_kernel<<<dim3(BT / 64, UU / 64), 256>>>(x, Wq, bq, Wk, bk, Wv, bv);

    cudaFuncSetAttribute(attn_kernel, cudaFuncAttributeMaxDynamicSharedMemorySize, ATTN_SMEM_BYTES);
    attn_kernel<<<dim3(TT / TQ, BB), 256, ATTN_SMEM_BYTES>>>();

    proj_kernel<<<dim3(BT / 64, CC / 64), 256>>>(x, Wa, ba, out);
}

// round 2
// speedup vs baseline: 1.6548x; 1.6548x over previous
#include <cuda_runtime.h>
#include <math.h>

#define BB 8
#define TT 2048
#define CC 512
#define UU 256
#define BT (BB*TT)

// Scratch (allocation-free rule: device globals)
__device__ float g_Q[BT*UU];
__device__ float g_K[BT*UU];
__device__ float g_V[BT*UU];
__device__ float g_A[BT*UU];

// ---------------------------------------------------------------------------
// Kernel 1: fused QKV projection.  [BT, C] @ [C, U] x3, shared x tile.
// ---------------------------------------------------------------------------
__global__ __launch_bounds__(256) void qkv_kernel(
    const float* __restrict__ x,
    const float* __restrict__ Wq, const float* __restrict__ bq,
    const float* __restrict__ Wk, const float* __restrict__ bk,
    const float* __restrict__ Wv, const float* __restrict__ bv)
{
    __shared__ float Xs[16][68];
    __shared__ float Wqs[16][68];
    __shared__ float Wks[16][68];
    __shared__ float Wvs[16][68];

    const int m0 = blockIdx.x * 64;
    const int n0 = blockIdx.y * 64;
    const int tid = threadIdx.x;
    const int tm = tid >> 4;
    const int tn = tid & 15;

    const int lr  = tid >> 2;
    const int lc4 = (tid & 3) * 4;
    const int wk  = tid >> 4;
    const int wn4 = (tid & 15) * 4;

    float aq[4][4] = {}, ak[4][4] = {}, av[4][4] = {};

    for (int k0 = 0; k0 < CC; k0 += 16) {
        __syncthreads();
        float4 xv = *reinterpret_cast<const float4*>(&x[(size_t)(m0 + lr) * CC + k0 + lc4]);
        Xs[lc4 + 0][lr] = xv.x;
        Xs[lc4 + 1][lr] = xv.y;
        Xs[lc4 + 2][lr] = xv.z;
        Xs[lc4 + 3][lr] = xv.w;
        float4 wq4 = *reinterpret_cast<const float4*>(&Wq[(size_t)(k0 + wk) * UU + n0 + wn4]);
        float4 wk4 = *reinterpret_cast<const float4*>(&Wk[(size_t)(k0 + wk) * UU + n0 + wn4]);
        float4 wv4 = *reinterpret_cast<const float4*>(&Wv[(size_t)(k0 + wk) * UU + n0 + wn4]);
        Wqs[wk][wn4 + 0] = wq4.x; Wqs[wk][wn4 + 1] = wq4.y; Wqs[wk][wn4 + 2] = wq4.z; Wqs[wk][wn4 + 3] = wq4.w;
        Wks[wk][wn4 + 0] = wk4.x; Wks[wk][wn4 + 1] = wk4.y; Wks[wk][wn4 + 2] = wk4.z; Wks[wk][wn4 + 3] = wk4.w;
        Wvs[wk][wn4 + 0] = wv4.x; Wvs[wk][wn4 + 1] = wv4.y; Wvs[wk][wn4 + 2] = wv4.z; Wvs[wk][wn4 + 3] = wv4.w;
        __syncthreads();

        #pragma unroll
        for (int k = 0; k < 16; k++) {
            float a[4];
            #pragma unroll
            for (int i = 0; i < 4; i++) a[i] = Xs[k][tm * 4 + i];
            float q4[4], k4[4], v4[4];
            #pragma unroll
            for (int j = 0; j < 4; j++) {
                q4[j] = Wqs[k][tn * 4 + j];
                k4[j] = Wks[k][tn * 4 + j];
                v4[j] = Wvs[k][tn * 4 + j];
            }
            #pragma unroll
            for (int i = 0; i < 4; i++)
                #pragma unroll
                for (int j = 0; j < 4; j++) {
                    aq[i][j] = fmaf(a[i], q4[j], aq[i][j]);
                    ak[i][j] = fmaf(a[i], k4[j], ak[i][j]);
                    av[i][j] = fmaf(a[i], v4[j], av[i][j]);
                }
        }
    }

    #pragma unroll
    for (int i = 0; i < 4; i++) {
        const int m = m0 + tm * 4 + i;
        #pragma unroll
        for (int j = 0; j < 4; j++) {
            const int n = n0 + tn * 4 + j;
            g_Q[(size_t)m * UU + n] = aq[i][j] + bq[n];
            g_K[(size_t)m * UU + n] = ak[i][j] + bk[n];
            g_V[(size_t)m * UU + n] = av[i][j] + bv[n];
        }
    }
}

// ---------------------------------------------------------------------------
// Kernel 2: flash attention v2.
// Block: TQ=64 queries, 256 threads, 2 CTAs/SM.
// Q stored u-major in smem (scaled). Per key tile (64):
//   S: 4 u-chunks, 4x4 micro-tile, float4 LDS both operands.
//   softmax: 4 threads/row, shuffle reduce.
//   PV: 4 d-chunks, V staged d-major, thread owns 4q x 4d per chunk (16 dims tot).
// ---------------------------------------------------------------------------
#define TQ 64
#define TK 64
#define QS_STRIDE 68
#define ATTN_SMEM_FLOATS (UU*QS_STRIDE + TK*QS_STRIDE + TQ*QS_STRIDE + 3*TQ)
#define ATTN_SMEM_BYTES  (ATTN_SMEM_FLOATS * 4)

__global__ __launch_bounds__(256, 2) void attn_kernel()
{
    extern __shared__ float sm[];
    float* Qs   = sm;                         // [256 u][68]  (scaled, transposed)
    float* KVs  = Qs + UU * QS_STRIDE;        // [64][68]  K-chunk (u-major) / V-chunk (s-major)
    float* Ps   = KVs + TK * QS_STRIDE;       // [64 q][68 k]
    float* mrow = Ps + TQ * QS_STRIDE;
    float* lrow = mrow + TQ;
    float* crow = lrow + TQ;

    const int b   = blockIdx.y;
    const int q0  = blockIdx.x * TQ;
    const int tid = threadIdx.x;

    const float scale = 0.0625f;              // 1/sqrt(256)

    // --- load Q transposed: Qs[u][q] = Q[q][u]*scale ---
    {
        const int q  = tid & 63;
        const int u0 = (tid >> 6) * 64;
        const float* src = &g_Q[(size_t)(b * TT + q0 + q) * UU + u0];
        #pragma unroll
        for (int i = 0; i < 16; i++) {
            float4 v = *reinterpret_cast<const float4*>(src + i * 4);
            Qs[(u0 + i * 4 + 0) * QS_STRIDE + q] = v.x * scale;
            Qs[(u0 + i * 4 + 1) * QS_STRIDE + q] = v.y * scale;
            Qs[(u0 + i * 4 + 2) * QS_STRIDE + q] = v.z * scale;
            Qs[(u0 + i * 4 + 3) * QS_STRIDE + q] = v.w * scale;
        }
    }
    if (tid < TQ) { mrow[tid] = -1e30f; lrow[tid] = 0.0f; }

    const int tq = (tid >> 4) * 4;            // 0,4,...,60
    const int tk = (tid & 15) * 4;            // 0,4,...,60 (also d-group in PV)

    float O[4][16];
    #pragma unroll
    for (int i = 0; i < 4; i++)
        #pragma unroll
        for (int j = 0; j < 16; j++) O[i][j] = 0.0f;

    // staging indices
    const int sk  = tid & 63;                 // key / seq row
    const int sc0 = (tid >> 6) * 16;          // 16-col strip

    __syncthreads();

    for (int s0 = 0; s0 < TT; s0 += TK) {
        float Sacc[4][4] = {};

        // ---- S = Q @ K^T, 4 u-chunks of 64 ----
        for (int uc = 0; uc < UU; uc += 64) {
            __syncthreads();                  // KVs free
            {
                const float* src = &g_K[(size_t)(b * TT + s0 + sk) * UU + uc + sc0];
                #pragma unroll
                for (int i = 0; i < 4; i++) {
                    float4 v = *reinterpret_cast<const float4*>(src + i * 4);
                    KVs[(sc0 + i * 4 + 0) * QS_STRIDE + sk] = v.x;
                    KVs[(sc0 + i * 4 + 1) * QS_STRIDE + sk] = v.y;
                    KVs[(sc0 + i * 4 + 2) * QS_STRIDE + sk] = v.z;
                    KVs[(sc0 + i * 4 + 3) * QS_STRIDE + sk] = v.w;
                }
            }
            __syncthreads();
            #pragma unroll 16
            for (int u = 0; u < 64; u++) {
                float4 qa = *reinterpret_cast<const float4*>(&Qs[(uc + u) * QS_STRIDE + tq]);
                float4 kb = *reinterpret_cast<const float4*>(&KVs[u * QS_STRIDE + tk]);
                const float a[4] = {qa.x, qa.y, qa.z, qa.w};
                const float c[4] = {kb.x, kb.y, kb.z, kb.w};
                #pragma unroll
                for (int i = 0; i < 4; i++)
                    #pragma unroll
                    for (int j = 0; j < 4; j++)
                        Sacc[i][j] = fmaf(a[i], c[j], Sacc[i][j]);
            }
        }

        // stage S -> Ps
        #pragma unroll
        for (int i = 0; i < 4; i++) {
            float4 sv = make_float4(Sacc[i][0], Sacc[i][1], Sacc[i][2], Sacc[i][3]);
            *reinterpret_cast<float4*>(&Ps[(tq + i) * QS_STRIDE + tk]) = sv;
        }
        __syncthreads();

        // ---- online softmax: 4 threads per row ----
        {
            const int row = tid >> 2;
            const int cg  = (tid & 3) * 16;
            const float m_old = mrow[row];
            float rmax = m_old;
            #pragma unroll
            for (int j = 0; j < 16; j++)
                rmax = fmaxf(rmax, Ps[row * QS_STRIDE + cg + j]);
            rmax = fmaxf(rmax, __shfl_xor_sync(0xFFFFFFFF, rmax, 1));
            rmax = fmaxf(rmax, __shfl_xor_sync(0xFFFFFFFF, rmax, 2));
            float sum = 0.0f;
            #pragma unroll
            for (int j = 0; j < 16; j++) {
                const float p = __expf(Ps[row * QS_STRIDE + cg + j] - rmax);
                Ps[row * QS_STRIDE + cg + j] = p;
                sum += p;
            }
            sum += __shfl_xor_sync(0xFFFFFFFF, sum, 1);
            sum += __shfl_xor_sync(0xFFFFFFFF, sum, 2);
            if ((tid & 3) == 0) {
                const float cc = __expf(m_old - rmax);
                lrow[row] = lrow[row] * cc + sum;
                mrow[row] = rmax;
                crow[row] = cc;
            }
        }
        __syncthreads();

        // rescale O
        {
            float cc[4];
            #pragma unroll
            for (int i = 0; i < 4; i++) cc[i] = crow[tq + i];
            #pragma unroll
            for (int i = 0; i < 4; i++)
                #pragma unroll
                for (int j = 0; j < 16; j++) O[i][j] *= cc[i];
        }

        // ---- O += P @ V, 4 d-chunks of 64 ----
        for (int dc = 0; dc < 4; dc++) {
            __syncthreads();                  // KVs free
            {
                const float* src = &g_V[(size_t)(b * TT + s0 + sk) * UU + dc * 64 + sc0];
                #pragma unroll
                for (int i = 0; i < 4; i++) {
                    float4 v = *reinterpret_cast<const float4*>(src + i * 4);
                    *reinterpret_cast<float4*>(&KVs[sk * QS_STRIDE + sc0 + i * 4]) = v;
                }
            }
            __syncthreads();
            #pragma unroll 16
            for (int s = 0; s < 64; s++) {
                float pf[4];
                #pragma unroll
                for (int i = 0; i < 4; i++) pf[i] = Ps[(tq + i) * QS_STRIDE + s];
                float4 vv = *reinterpret_cast<const float4*>(&KVs[s * QS_STRIDE + tk]);
                const float v[4] = {vv.x, vv.y, vv.z, vv.w};
                #pragma unroll
                for (int i = 0; i < 4; i++)
                    #pragma unroll
                    for (int j = 0; j < 4; j++)
                        O[i][dc * 4 + j] = fmaf(pf[i], v[j], O[i][dc * 4 + j]);
            }
        }
    }

    // ---- write out: A[q][d] = O / l ----
    {
        float inv[4];
        #pragma unroll
        for (int i = 0; i < 4; i++) inv[i] = 1.0f / lrow[tq + i];
        #pragma unroll
        for (int i = 0; i < 4; i++) {
            float* dst = &g_A[(size_t)(b * TT + q0 + tq + i) * UU];
            #pragma unroll
            for (int dc = 0; dc < 4; dc++) {
                float4 ov = make_float4(O[i][dc * 4 + 0] * inv[i],
                                        O[i][dc * 4 + 1] * inv[i],
                                        O[i][dc * 4 + 2] * inv[i],
                                        O[i][dc * 4 + 3] * inv[i]);
                *reinterpret_cast<float4*>(dst + dc * 64 + tk) = ov;
            }
        }
    }
}

// ---------------------------------------------------------------------------
// Kernel 3: output projection + residual.  out = x + A @ Wa + ba
// ---------------------------------------------------------------------------
__global__ __launch_bounds__(256) void proj_kernel(
    const float* __restrict__ x,
    const float* __restrict__ Wa, const float* __restrict__ ba,
    float* __restrict__ out)
{
    __shared__ float As[16][68];
    __shared__ float Ws[16][68];

    const int m0 = blockIdx.x * 64;
    const int n0 = blockIdx.y * 64;
    const int tid = threadIdx.x;
    const int tm = tid >> 4;
    const int tn = tid & 15;

    const int lr  = tid >> 2;
    const int lc4 = (tid & 3) * 4;
    const int wk  = tid >> 4;
    const int wn4 = (tid & 15) * 4;

    float acc[4][4] = {};

    for (int k0 = 0; k0 < UU; k0 += 16) {
        __syncthreads();
        float4 av = *reinterpret_cast<const float4*>(&g_A[(size_t)(m0 + lr) * UU + k0 + lc4]);
        As[lc4 + 0][lr] = av.x;
        As[lc4 + 1][lr] = av.y;
        As[lc4 + 2][lr] = av.z;
        As[lc4 + 3][lr] = av.w;
        float4 wv = *reinterpret_cast<const float4*>(&Wa[(size_t)(k0 + wk) * CC + n0 + wn4]);
        Ws[wk][wn4 + 0] = wv.x; Ws[wk][wn4 + 1] = wv.y; Ws[wk][wn4 + 2] = wv.z; Ws[wk][wn4 + 3] = wv.w;
        __syncthreads();

        #pragma unroll
        for (int k = 0; k < 16; k++) {
            float a[4];
            #pragma unroll
            for (int i = 0; i < 4; i++) a[i] = As[k][tm * 4 + i];
            float w4[4];
            #pragma unroll
            for (int j = 0; j < 4; j++) w4[j] = Ws[k][tn * 4 + j];
            #pragma unroll
            for (int i = 0; i < 4; i++)
                #pragma unroll
                for (int j = 0; j < 4; j++)
                    acc[i][j] = fmaf(a[i], w4[j], acc[i][j]);
        }
    }

    #pragma unroll
    for (int i = 0; i < 4; i++) {
        const int m = m0 + tm * 4 + i;
        #pragma unroll
        for (int j = 0; j < 4; j++) {
            const int n = n0 + tn * 4 + j;
            out[(size_t)m * CC + n] = acc[i][j] + x[(size_t)m * CC + n] + ba[n];
        }
    }
}

// ---------------------------------------------------------------------------
extern "C" void kernel_launch(void* const* d_in, const int* in_sizes, int n_in,
                              void* d_out, int out_size)
{
    const float* x  = (const float*)d_in[0];
    const float* Wq = (const float*)d_in[1];
    const float* bq = (const float*)d_in[2];
    const float* Wk = (const float*)d_in[3];
    const float* bk = (const float*)d_in[4];
    const float* Wv = (const float*)d_in[5];
    const float* bv = (const float*)d_in[6];
    const float* Wa = (const float*)d_in[7];
    const float* ba = (const float*)d_in[8];
    float* out = (float*)d_out;

    qkv_kernel<<<dim3(BT / 64, UU / 64), 256>>>(x, Wq, bq, Wk, bk, Wv, bv);

    cudaFuncSetAttribute(attn_kernel, cudaFuncAttributeMaxDynamicSharedMemorySize, ATTN_SMEM_BYTES);
    attn_kernel<<<dim3(TT / TQ, BB), 256, ATTN_SMEM_BYTES>>>();

    proj_kernel<<<dim3(BT / 64, CC / 64), 256>>>(x, Wa, ba, out);
}